// round 2
// baseline (speedup 1.0000x reference)
#include <cuda_runtime.h>
#include <math.h>

// Problem constants (fixed shapes from reference)
#define T_TOK 8192          // B*S tokens
#define HDIM  1024
#define FDIM  3584
#define NEXP  8
#define TOPK  2
#define BM    128           // row-tile (tokens)
#define ROWS_MAX (T_TOK*TOPK + NEXP*BM)   // 17408 padded rows max
#define OUT_ELEMS (T_TOK*HDIM)            // 8388608 (moe output), logits follow

// ---------------- device scratch (allocation-free) ----------------
__device__ float g_hgate[(size_t)ROWS_MAX * FDIM];   // ~250 MB
__device__ int   g_row_token[ROWS_MAX];
__device__ float g_row_weight[ROWS_MAX];
__device__ int   g_counts[NEXP];
__device__ int   g_offsets[NEXP + 1];
__device__ int   g_cursor[NEXP];
__device__ int   g_total_rows;
__device__ int   g_tok_expert[T_TOK * TOPK];
__device__ float g_tok_weight[T_TOK * TOPK];

// ---------------- 0) init: zero output, reset row map + counts ----------------
__global__ void init_kernel(float* __restrict__ out) {
    int i = blockIdx.x * blockDim.x + threadIdx.x;
    if (i < OUT_ELEMS) out[i] = 0.0f;
    if (i < ROWS_MAX) { g_row_token[i] = -1; g_row_weight[i] = 0.0f; }
    if (i < NEXP) g_counts[i] = 0;
}

// ---------------- 1) router: logits, softmax, top-2 ----------------
// 1 warp per token, gate_w cached in smem (8*1024*4 = 32KB)
__global__ void router_kernel(const float* __restrict__ x,
                              const float* __restrict__ gate_w,
                              float* __restrict__ logits_out) {
    __shared__ float s_gate[NEXP * HDIM];
    for (int i = threadIdx.x; i < NEXP * HDIM; i += blockDim.x)
        s_gate[i] = gate_w[i];
    __syncthreads();

    int warp = threadIdx.x >> 5, lane = threadIdx.x & 31;
    int t = blockIdx.x * (blockDim.x >> 5) + warp;
    if (t >= T_TOK) return;

    float acc[NEXP];
#pragma unroll
    for (int e = 0; e < NEXP; e++) acc[e] = 0.0f;
    const float* xr = x + (size_t)t * HDIM;
    for (int j = lane; j < HDIM; j += 32) {
        float xv = xr[j];
#pragma unroll
        for (int e = 0; e < NEXP; e++) acc[e] += xv * s_gate[e * HDIM + j];
    }
#pragma unroll
    for (int e = 0; e < NEXP; e++) {
#pragma unroll
        for (int o = 16; o > 0; o >>= 1)
            acc[e] += __shfl_xor_sync(0xffffffffu, acc[e], o);
    }
    if (lane == 0) {
        float mx = acc[0];
#pragma unroll
        for (int e = 1; e < NEXP; e++) mx = fmaxf(mx, acc[e]);
        float p[NEXP], s = 0.0f;
#pragma unroll
        for (int e = 0; e < NEXP; e++) { p[e] = expf(acc[e] - mx); s += p[e]; }
        float inv = 1.0f / s;
#pragma unroll
        for (int e = 0; e < NEXP; e++) p[e] *= inv;
        // top-2 (ties -> lower index, matching lax.top_k)
        int i0 = 0;
#pragma unroll
        for (int e = 1; e < NEXP; e++) if (p[e] > p[i0]) i0 = e;
        int i1 = (i0 == 0) ? 1 : 0;
#pragma unroll
        for (int e = 0; e < NEXP; e++) if (e != i0 && p[e] > p[i1]) i1 = e;
        float w0 = p[i0], w1 = p[i1], ws = 1.0f / (w0 + w1);
        w0 *= ws; w1 *= ws;
#pragma unroll
        for (int e = 0; e < NEXP; e++) logits_out[(size_t)t * NEXP + e] = acc[e];
        g_tok_expert[t * 2 + 0] = i0; g_tok_expert[t * 2 + 1] = i1;
        g_tok_weight[t * 2 + 0] = w0; g_tok_weight[t * 2 + 1] = w1;
        atomicAdd(&g_counts[i0], 1);
        atomicAdd(&g_counts[i1], 1);
    }
}

// ---------------- 2) scan: padded expert segment offsets ----------------
__global__ void scan_kernel() {
    int total = 0;
    for (int e = 0; e < NEXP; e++) {
        g_offsets[e] = total;
        g_cursor[e]  = total;
        int padded = ((g_counts[e] + BM - 1) / BM) * BM;
        total += padded;
    }
    g_offsets[NEXP] = total;
    g_total_rows = total;
}

// ---------------- 3) scatter tokens into expert-grouped rows ----------------
__global__ void scatter_kernel() {
    int t = blockIdx.x * blockDim.x + threadIdx.x;
    if (t >= T_TOK) return;
#pragma unroll
    for (int s = 0; s < TOPK; s++) {
        int e = g_tok_expert[t * 2 + s];
        int p = atomicAdd(&g_cursor[e], 1);
        g_row_token[p]  = t;
        g_row_weight[p] = g_tok_weight[t * 2 + s];
    }
}

// ---------------- 4) GEMM1 (fused w1/w3 + SiLU*mul) ----------------
// hgate[r, n] = silu(x_t . w1[e,n,:]) * (x_t . w3[e,n,:])
// Tile: BM=128 rows x BN=64 f-cols x BK=16, 256 threads, TM=8 x TN=4 dual-acc
__global__ __launch_bounds__(256, 2)
void gemm1_kernel(const float* __restrict__ x,
                  const float* __restrict__ w1,
                  const float* __restrict__ w3) {
    int row0 = blockIdx.x * BM;
    if (row0 >= g_total_rows) return;
    int n0 = blockIdx.y * 64;

    int e = 0;
#pragma unroll
    for (int i = 0; i < NEXP; i++) if (row0 >= g_offsets[i + 1]) e = i + 1;

    __shared__ float As[BM][17];     // [m][k], padded
    __shared__ float B1s[16][68];    // [k][n], padded
    __shared__ float B3s[16][68];

    int tid = threadIdx.x;
    int ty = tid >> 4, tx = tid & 15;

    const float* w1e = w1 + (size_t)e * FDIM * HDIM;
    const float* w3e = w3 + (size_t)e * FDIM * HDIM;

    // cache token ids for the 8 A-rows this thread loads (m independent of k0)
    int tokc[8];
#pragma unroll
    for (int i = 0; i < 8; i++) {
        int idx = tid + i * 256;
        tokc[i] = g_row_token[row0 + (idx >> 4)];
    }

    float acc1[8][4], acc3[8][4];
#pragma unroll
    for (int i = 0; i < 8; i++)
#pragma unroll
        for (int j = 0; j < 4; j++) { acc1[i][j] = 0.0f; acc3[i][j] = 0.0f; }

    for (int k0 = 0; k0 < HDIM; k0 += 16) {
#pragma unroll
        for (int i = 0; i < 8; i++) {
            int idx = tid + i * 256;
            int m = idx >> 4, k = idx & 15;
            int t = tokc[i];
            As[m][k] = (t >= 0) ? x[(size_t)t * HDIM + k0 + k] : 0.0f;
        }
#pragma unroll
        for (int i = 0; i < 4; i++) {
            int idx = tid + i * 256;
            int n = idx >> 4, k = idx & 15;
            size_t off = (size_t)(n0 + n) * HDIM + k0 + k;
            B1s[k][n] = w1e[off];
            B3s[k][n] = w3e[off];
        }
        __syncthreads();
#pragma unroll
        for (int k = 0; k < 16; k++) {
            float a[8], b1[4], b3[4];
#pragma unroll
            for (int i = 0; i < 8; i++) a[i] = As[ty * 8 + i][k];
#pragma unroll
            for (int j = 0; j < 4; j++) { b1[j] = B1s[k][tx * 4 + j]; b3[j] = B3s[k][tx * 4 + j]; }
#pragma unroll
            for (int i = 0; i < 8; i++)
#pragma unroll
                for (int j = 0; j < 4; j++) {
                    acc1[i][j] += a[i] * b1[j];
                    acc3[i][j] += a[i] * b3[j];
                }
        }
        __syncthreads();
    }

#pragma unroll
    for (int i = 0; i < 8; i++) {
        int r = row0 + ty * 8 + i;
#pragma unroll
        for (int j = 0; j < 4; j++) {
            int n = n0 + tx * 4 + j;
            float g = acc1[i][j];
            float h = (g / (1.0f + expf(-g))) * acc3[i][j];
            g_hgate[(size_t)r * FDIM + n] = h;
        }
    }
}

// ---------------- 5) GEMM2: out[t,:] += weight * (hgate[r,:] @ w2[e]^T) -------
__global__ __launch_bounds__(256, 2)
void gemm2_kernel(const float* __restrict__ w2, float* __restrict__ out) {
    int row0 = blockIdx.x * BM;
    if (row0 >= g_total_rows) return;
    int n0 = blockIdx.y * 64;

    int e = 0;
#pragma unroll
    for (int i = 0; i < NEXP; i++) if (row0 >= g_offsets[i + 1]) e = i + 1;

    __shared__ float As[BM][17];
    __shared__ float Bs[16][68];

    int tid = threadIdx.x;
    int ty = tid >> 4, tx = tid & 15;
    const float* w2e = w2 + (size_t)e * HDIM * FDIM;

    float acc[8][4];
#pragma unroll
    for (int i = 0; i < 8; i++)
#pragma unroll
        for (int j = 0; j < 4; j++) acc[i][j] = 0.0f;

    for (int k0 = 0; k0 < FDIM; k0 += 16) {
#pragma unroll
        for (int i = 0; i < 8; i++) {
            int idx = tid + i * 256;
            int m = idx >> 4, k = idx & 15;
            As[m][k] = g_hgate[(size_t)(row0 + m) * FDIM + k0 + k];
        }
#pragma unroll
        for (int i = 0; i < 4; i++) {
            int idx = tid + i * 256;
            int n = idx >> 4, k = idx & 15;
            Bs[k][n] = w2e[(size_t)(n0 + n) * FDIM + k0 + k];
        }
        __syncthreads();
#pragma unroll
        for (int k = 0; k < 16; k++) {
            float a[8], b[4];
#pragma unroll
            for (int i = 0; i < 8; i++) a[i] = As[ty * 8 + i][k];
#pragma unroll
            for (int j = 0; j < 4; j++) b[j] = Bs[k][tx * 4 + j];
#pragma unroll
            for (int i = 0; i < 8; i++)
#pragma unroll
                for (int j = 0; j < 4; j++) acc[i][j] += a[i] * b[j];
        }
        __syncthreads();
    }

#pragma unroll
    for (int i = 0; i < 8; i++) {
        int r = row0 + ty * 8 + i;
        int t = g_row_token[r];
        if (t < 0) continue;
        float w = g_row_weight[r];
#pragma unroll
        for (int j = 0; j < 4; j++) {
            atomicAdd(&out[(size_t)t * HDIM + n0 + tx * 4 + j], acc[i][j] * w);
        }
    }
}

// ---------------- launcher ----------------
extern "C" void kernel_launch(void* const* d_in, const int* in_sizes, int n_in,
                              void* d_out, int out_size) {
    const float* x      = (const float*)d_in[0];   // [T, H]
    const float* gate_w = (const float*)d_in[1];   // [E, H]
    const float* w1     = (const float*)d_in[2];   // [E, F, H]
    const float* w2     = (const float*)d_in[3];   // [E, H, F]
    const float* w3     = (const float*)d_in[4];   // [E, F, H]
    float* out          = (float*)d_out;           // [T*H] moe out, then [T*E] logits
    float* logits_out   = out + (size_t)OUT_ELEMS;

    (void)in_sizes; (void)n_in; (void)out_size;

    // 0) init
    init_kernel<<<(OUT_ELEMS + 255) / 256, 256>>>(out);
    // 1) router (8 warps/block -> 8 tokens per block)
    router_kernel<<<T_TOK / 8, 256>>>(x, gate_w, logits_out);
    // 2) scan
    scan_kernel<<<1, 1>>>();
    // 3) scatter
    scatter_kernel<<<(T_TOK + 255) / 256, 256>>>();
    // 4) GEMM1: rows x F
    dim3 g1(ROWS_MAX / BM, FDIM / 64);
    gemm1_kernel<<<g1, 256>>>(x, w1, w3);
    // 5) GEMM2: rows x H
    dim3 g2(ROWS_MAX / BM, HDIM / 64);
    gemm2_kernel<<<g2, 256>>>(w2, out);
}

// round 5
// speedup vs baseline: 2.6827x; 2.6827x over previous
#include <cuda_runtime.h>
#include <cuda_bf16.h>
#include <math.h>
#include <stdint.h>

// Problem constants
#define T_TOK 8192
#define HDIM  1024
#define FDIM  3584
#define NEXP  8
#define TOPK  2
#define BM    128
#define ROWS_MAX (T_TOK*TOPK + NEXP*BM)   // 17408
#define OUT_ELEMS (T_TOK*HDIM)

// Smem geometry (bf16 elements). Row stride 40 bf16 (=20 u32) -> conflict-free frags.
#define ASTR  40
#define A_ELEMS (128*ASTR)        // 5120
#define B_ELEMS (64*ASTR)         // 2560
// gemm1 stage: Ab, As, B1b, B1s, B3b, B3s
#define G1_AB   0
#define G1_AS   (A_ELEMS)
#define G1_B1B  (2*A_ELEMS)
#define G1_B1S  (2*A_ELEMS + B_ELEMS)
#define G1_B3B  (2*A_ELEMS + 2*B_ELEMS)
#define G1_B3S  (2*A_ELEMS + 3*B_ELEMS)
#define G1_STAGE (2*A_ELEMS + 4*B_ELEMS)  // 20480 bf16 = 40960 B
// gemm2 stage: Ab, As, Bb, Bs
#define G2_AB   0
#define G2_AS   (A_ELEMS)
#define G2_BB   (2*A_ELEMS)
#define G2_BS   (2*A_ELEMS + B_ELEMS)
#define G2_STAGE (2*A_ELEMS + 2*B_ELEMS)  // 15360 bf16 = 30720 B

// ---------------- device scratch ----------------
// hgate stored as packed bf16 pair per element: lo = big, hi = small
__device__ uint32_t g_hgate[(size_t)ROWS_MAX * FDIM];
__device__ int   g_row_token[ROWS_MAX];
__device__ float g_row_weight[ROWS_MAX];
__device__ int   g_counts[NEXP];
__device__ int   g_offsets[NEXP + 1];
__device__ int   g_cursor[NEXP];
__device__ int   g_total_rows;
__device__ int   g_tok_expert[T_TOK * TOPK];
__device__ float g_tok_weight[T_TOK * TOPK];

// ---------------- helpers ----------------
__device__ __forceinline__ uint32_t pack2(float x, float y) {
    __nv_bfloat162 t = __floats2bfloat162_rn(x, y);   // lo=x, hi=y
    return *(uint32_t*)&t;
}
__device__ __forceinline__ void split1(float v, float& b, float& s) {
    __nv_bfloat16 hb = __float2bfloat16(v);
    b = __bfloat162float(hb);
    s = v - b;
}
// split a float4 into big/small packed-uint2 (4 bf16 each)
__device__ __forceinline__ void split4p(float4 v, uint2& big, uint2& sml) {
    float b0,s0,b1,s1,b2,s2,b3,s3;
    split1(v.x,b0,s0); split1(v.y,b1,s1); split1(v.z,b2,s2); split1(v.w,b3,s3);
    big.x = pack2(b0,b1); big.y = pack2(b2,b3);
    sml.x = pack2(s0,s1); sml.y = pack2(s2,s3);
}
__device__ __forceinline__ void mma16816(float (&d)[4], const uint32_t (&a)[4],
                                         uint32_t b0, uint32_t b1) {
    asm volatile(
        "mma.sync.aligned.m16n8k16.row.col.f32.bf16.bf16.f32 "
        "{%0,%1,%2,%3}, {%4,%5,%6,%7}, {%8,%9}, {%0,%1,%2,%3};"
        : "+f"(d[0]), "+f"(d[1]), "+f"(d[2]), "+f"(d[3])
        : "r"(a[0]), "r"(a[1]), "r"(a[2]), "r"(a[3]), "r"(b0), "r"(b1));
}

// ---------------- 0) init ----------------
__global__ void init_kernel(float* __restrict__ out) {
    int i = blockIdx.x * blockDim.x + threadIdx.x;
    if (i < OUT_ELEMS) out[i] = 0.0f;
    if (i < ROWS_MAX) { g_row_token[i] = -1; g_row_weight[i] = 0.0f; }
    if (i < NEXP) g_counts[i] = 0;
}

// ---------------- 1) router ----------------
__global__ void router_kernel(const float* __restrict__ x,
                              const float* __restrict__ gate_w,
                              float* __restrict__ logits_out) {
    __shared__ float s_gate[NEXP * HDIM];
    for (int i = threadIdx.x; i < NEXP * HDIM; i += blockDim.x)
        s_gate[i] = gate_w[i];
    __syncthreads();

    int warp = threadIdx.x >> 5, lane = threadIdx.x & 31;
    int t = blockIdx.x * (blockDim.x >> 5) + warp;
    if (t >= T_TOK) return;

    float acc[NEXP];
#pragma unroll
    for (int e = 0; e < NEXP; e++) acc[e] = 0.0f;
    const float* xr = x + (size_t)t * HDIM;
    for (int j = lane; j < HDIM; j += 32) {
        float xv = xr[j];
#pragma unroll
        for (int e = 0; e < NEXP; e++) acc[e] += xv * s_gate[e * HDIM + j];
    }
#pragma unroll
    for (int e = 0; e < NEXP; e++) {
#pragma unroll
        for (int o = 16; o > 0; o >>= 1)
            acc[e] += __shfl_xor_sync(0xffffffffu, acc[e], o);
    }
    if (lane == 0) {
        float mx = acc[0];
#pragma unroll
        for (int e = 1; e < NEXP; e++) mx = fmaxf(mx, acc[e]);
        float p[NEXP], s = 0.0f;
#pragma unroll
        for (int e = 0; e < NEXP; e++) { p[e] = expf(acc[e] - mx); s += p[e]; }
        float inv = 1.0f / s;
#pragma unroll
        for (int e = 0; e < NEXP; e++) p[e] *= inv;
        int i0 = 0;
#pragma unroll
        for (int e = 1; e < NEXP; e++) if (p[e] > p[i0]) i0 = e;
        int i1 = (i0 == 0) ? 1 : 0;
#pragma unroll
        for (int e = 0; e < NEXP; e++) if (e != i0 && p[e] > p[i1]) i1 = e;
        float w0 = p[i0], w1 = p[i1], ws = 1.0f / (w0 + w1);
        w0 *= ws; w1 *= ws;
#pragma unroll
        for (int e = 0; e < NEXP; e++) logits_out[(size_t)t * NEXP + e] = acc[e];
        g_tok_expert[t * 2 + 0] = i0; g_tok_expert[t * 2 + 1] = i1;
        g_tok_weight[t * 2 + 0] = w0; g_tok_weight[t * 2 + 1] = w1;
        atomicAdd(&g_counts[i0], 1);
        atomicAdd(&g_counts[i1], 1);
    }
}

// ---------------- 2) scan ----------------
__global__ void scan_kernel() {
    int total = 0;
    for (int e = 0; e < NEXP; e++) {
        g_offsets[e] = total;
        g_cursor[e]  = total;
        int padded = ((g_counts[e] + BM - 1) / BM) * BM;
        total += padded;
    }
    g_offsets[NEXP] = total;
    g_total_rows = total;
}

// ---------------- 3) scatter ----------------
__global__ void scatter_kernel() {
    int t = blockIdx.x * blockDim.x + threadIdx.x;
    if (t >= T_TOK) return;
#pragma unroll
    for (int s = 0; s < TOPK; s++) {
        int e = g_tok_expert[t * 2 + s];
        int p = atomicAdd(&g_cursor[e], 1);
        g_row_token[p]  = t;
        g_row_weight[p] = g_tok_weight[t * 2 + s];
    }
}

// ---------------- 4) GEMM1: mma.sync bf16 split x3, fused w1/w3 + SiLU*mul ------
// CTA tile 128x64, BK=32, 8 warps (4m x 2n), warp tile 32x32, dual accumulators.
__global__ __launch_bounds__(256)
void gemm1_mma(const float* __restrict__ x,
               const float* __restrict__ w1,
               const float* __restrict__ w3) {
    int row0 = blockIdx.x * BM;
    if (row0 >= g_total_rows) return;
    int n0 = blockIdx.y * 64;

    int e = 0;
#pragma unroll
    for (int i = 0; i < NEXP; i++) if (row0 >= g_offsets[i + 1]) e = i + 1;

    extern __shared__ __nv_bfloat16 smem[];
    int tid = threadIdx.x, wid = tid >> 5, lane = tid & 31;
    int wm = wid & 3, wn = wid >> 2;

    const float* w1e = w1 + (size_t)e * FDIM * HDIM;
    const float* w3e = w3 + (size_t)e * FDIM * HDIM;

    int tok[4];
#pragma unroll
    for (int i = 0; i < 4; i++) tok[i] = g_row_token[row0 + ((tid + i * 256) >> 3)];

    float acc1[2][4][4], acc3[2][4][4];
#pragma unroll
    for (int m = 0; m < 2; m++)
#pragma unroll
        for (int j = 0; j < 4; j++)
#pragma unroll
            for (int q = 0; q < 4; q++) { acc1[m][j][q] = 0.0f; acc3[m][j][q] = 0.0f; }

    float4 ra[4], rb1[2], rb3[2];
    const int NC = HDIM / 32;

    // gmem load of chunk c into regs
    auto loadg = [&](int c) {
        int k0 = c * 32;
#pragma unroll
        for (int i = 0; i < 4; i++) {
            int v = tid + i * 256;
            int col4 = v & 7;
            ra[i] = (tok[i] >= 0)
                  ? *(const float4*)(x + (size_t)tok[i] * HDIM + k0 + col4 * 4)
                  : make_float4(0.f, 0.f, 0.f, 0.f);
        }
#pragma unroll
        for (int i = 0; i < 2; i++) {
            int v = tid + i * 256;
            int row = v >> 3, col4 = v & 7;
            rb1[i] = *(const float4*)(w1e + (size_t)(n0 + row) * HDIM + k0 + col4 * 4);
            rb3[i] = *(const float4*)(w3e + (size_t)(n0 + row) * HDIM + k0 + col4 * 4);
        }
    };
    // split + store regs into smem stage
    auto stash = [&](int stg) {
        __nv_bfloat16* st = smem + stg * G1_STAGE;
#pragma unroll
        for (int i = 0; i < 4; i++) {
            int v = tid + i * 256;
            int row = v >> 3, col4 = v & 7;
            uint2 big, sml; split4p(ra[i], big, sml);
            int off = row * ASTR + col4 * 4;
            *(uint2*)(st + G1_AB + off) = big;
            *(uint2*)(st + G1_AS + off) = sml;
        }
#pragma unroll
        for (int i = 0; i < 2; i++) {
            int v = tid + i * 256;
            int row = v >> 3, col4 = v & 7;
            int off = row * ASTR + col4 * 4;
            uint2 big, sml;
            split4p(rb1[i], big, sml);
            *(uint2*)(st + G1_B1B + off) = big;
            *(uint2*)(st + G1_B1S + off) = sml;
            split4p(rb3[i], big, sml);
            *(uint2*)(st + G1_B3B + off) = big;
            *(uint2*)(st + G1_B3S + off) = sml;
        }
    };

    loadg(0); stash(0); __syncthreads();

    for (int c = 0; c < NC; c++) {
        if (c + 1 < NC) loadg(c + 1);
        const uint32_t* su = (const uint32_t*)(smem + (c & 1) * G1_STAGE);
#pragma unroll
        for (int kk = 0; kk < 2; kk++) {
            int kof = kk * 8;
            uint32_t Ab[2][4], As[2][4];
#pragma unroll
            for (int m = 0; m < 2; m++) {
                int r = wm * 32 + m * 16 + (lane >> 2);
                int base = r * (ASTR / 2) + (lane & 3) + kof;
                Ab[m][0] = su[G1_AB / 2 + base];
                Ab[m][1] = su[G1_AB / 2 + base + 8 * (ASTR / 2)];
                Ab[m][2] = su[G1_AB / 2 + base + 4];
                Ab[m][3] = su[G1_AB / 2 + base + 8 * (ASTR / 2) + 4];
                As[m][0] = su[G1_AS / 2 + base];
                As[m][1] = su[G1_AS / 2 + base + 8 * (ASTR / 2)];
                As[m][2] = su[G1_AS / 2 + base + 4];
                As[m][3] = su[G1_AS / 2 + base + 8 * (ASTR / 2) + 4];
            }
#pragma unroll
            for (int j = 0; j < 4; j++) {
                int col = wn * 32 + j * 8 + (lane >> 2);
                int base = col * (ASTR / 2) + (lane & 3) + kof;
                uint32_t b1b0 = su[G1_B1B / 2 + base], b1b1 = su[G1_B1B / 2 + base + 4];
                uint32_t b1s0 = su[G1_B1S / 2 + base], b1s1 = su[G1_B1S / 2 + base + 4];
                uint32_t b3b0 = su[G1_B3B / 2 + base], b3b1 = su[G1_B3B / 2 + base + 4];
                uint32_t b3s0 = su[G1_B3S / 2 + base], b3s1 = su[G1_B3S / 2 + base + 4];
#pragma unroll
                for (int m = 0; m < 2; m++) {
                    mma16816(acc1[m][j], Ab[m], b1b0, b1b1);
                    mma16816(acc1[m][j], Ab[m], b1s0, b1s1);
                    mma16816(acc1[m][j], As[m], b1b0, b1b1);
                    mma16816(acc3[m][j], Ab[m], b3b0, b3b1);
                    mma16816(acc3[m][j], Ab[m], b3s0, b3s1);
                    mma16816(acc3[m][j], As[m], b3b0, b3b1);
                }
            }
        }
        if (c + 1 < NC) stash((c + 1) & 1);
        __syncthreads();
    }

    // epilogue: h = silu(g) * u, pack (big,small) bf16 pair -> g_hgate
#pragma unroll
    for (int m = 0; m < 2; m++) {
        int rA = row0 + wm * 32 + m * 16 + (lane >> 2);
        int rB = rA + 8;
#pragma unroll
        for (int j = 0; j < 4; j++) {
            int col = n0 + wn * 32 + j * 8 + (lane & 3) * 2;
            float g0 = acc1[m][j][0], g1 = acc1[m][j][1];
            float g2 = acc1[m][j][2], g3 = acc1[m][j][3];
            float u0 = acc3[m][j][0], u1 = acc3[m][j][1];
            float u2 = acc3[m][j][2], u3 = acc3[m][j][3];
            float h0 = g0 / (1.0f + __expf(-g0)) * u0;
            float h1 = g1 / (1.0f + __expf(-g1)) * u1;
            float h2 = g2 / (1.0f + __expf(-g2)) * u2;
            float h3 = g3 / (1.0f + __expf(-g3)) * u3;
            float b, s;
            uint2 pA, pB;
            split1(h0, b, s); pA.x = pack2(b, s);
            split1(h1, b, s); pA.y = pack2(b, s);
            split1(h2, b, s); pB.x = pack2(b, s);
            split1(h3, b, s); pB.y = pack2(b, s);
            *(uint2*)(g_hgate + (size_t)rA * FDIM + col) = pA;
            *(uint2*)(g_hgate + (size_t)rB * FDIM + col) = pB;
        }
    }
}

// ---------------- 5) GEMM2: mma.sync bf16 split x3, hgate @ w2^T -> atomics -----
__global__ __launch_bounds__(256)
void gemm2_mma(const float* __restrict__ w2, float* __restrict__ out) {
    int row0 = blockIdx.x * BM;
    if (row0 >= g_total_rows) return;
    int n0 = blockIdx.y * 64;

    int e = 0;
#pragma unroll
    for (int i = 0; i < NEXP; i++) if (row0 >= g_offsets[i + 1]) e = i + 1;

    extern __shared__ __nv_bfloat16 smem[];
    int tid = threadIdx.x, wid = tid >> 5, lane = tid & 31;
    int wm = wid & 3, wn = wid >> 2;

    const float* w2e = w2 + (size_t)e * HDIM * FDIM;

    float acc[2][4][4];
#pragma unroll
    for (int m = 0; m < 2; m++)
#pragma unroll
        for (int j = 0; j < 4; j++)
#pragma unroll
            for (int q = 0; q < 4; q++) acc[m][j][q] = 0.0f;

    uint4 rha[4]; float4 rb[2];
    const int NC = FDIM / 32;

    auto loadg = [&](int c) {
        int k0 = c * 32;
#pragma unroll
        for (int i = 0; i < 4; i++) {
            int v = tid + i * 256;
            int row = v >> 3, col4 = v & 7;
            rha[i] = *(const uint4*)(g_hgate + (size_t)(row0 + row) * FDIM + k0 + col4 * 4);
        }
#pragma unroll
        for (int i = 0; i < 2; i++) {
            int v = tid + i * 256;
            int row = v >> 3, col4 = v & 7;
            rb[i] = *(const float4*)(w2e + (size_t)(n0 + row) * FDIM + k0 + col4 * 4);
        }
    };
    auto stash = [&](int stg) {
        __nv_bfloat16* st = smem + stg * G2_STAGE;
#pragma unroll
        for (int i = 0; i < 4; i++) {
            int v = tid + i * 256;
            int row = v >> 3, col4 = v & 7;
            int off = row * ASTR + col4 * 4;
            // unpack (big lo, small hi) pairs
            uint2 big, sml;
            big.x = (rha[i].x & 0xFFFFu) | ((rha[i].y & 0xFFFFu) << 16);
            sml.x = (rha[i].x >> 16)     | (rha[i].y & 0xFFFF0000u);
            big.y = (rha[i].z & 0xFFFFu) | ((rha[i].w & 0xFFFFu) << 16);
            sml.y = (rha[i].z >> 16)     | (rha[i].w & 0xFFFF0000u);
            *(uint2*)(st + G2_AB + off) = big;
            *(uint2*)(st + G2_AS + off) = sml;
        }
#pragma unroll
        for (int i = 0; i < 2; i++) {
            int v = tid + i * 256;
            int row = v >> 3, col4 = v & 7;
            int off = row * ASTR + col4 * 4;
            uint2 big, sml; split4p(rb[i], big, sml);
            *(uint2*)(st + G2_BB + off) = big;
            *(uint2*)(st + G2_BS + off) = sml;
        }
    };

    loadg(0); stash(0); __syncthreads();

    for (int c = 0; c < NC; c++) {
        if (c + 1 < NC) loadg(c + 1);
        const uint32_t* su = (const uint32_t*)(smem + (c & 1) * G2_STAGE);
#pragma unroll
        for (int kk = 0; kk < 2; kk++) {
            int kof = kk * 8;
            uint32_t Ab[2][4], As[2][4];
#pragma unroll
            for (int m = 0; m < 2; m++) {
                int r = wm * 32 + m * 16 + (lane >> 2);
                int base = r * (ASTR / 2) + (lane & 3) + kof;
                Ab[m][0] = su[G2_AB / 2 + base];
                Ab[m][1] = su[G2_AB / 2 + base + 8 * (ASTR / 2)];
                Ab[m][2] = su[G2_AB / 2 + base + 4];
                Ab[m][3] = su[G2_AB / 2 + base + 8 * (ASTR / 2) + 4];
                As[m][0] = su[G2_AS / 2 + base];
                As[m][1] = su[G2_AS / 2 + base + 8 * (ASTR / 2)];
                As[m][2] = su[G2_AS / 2 + base + 4];
                As[m][3] = su[G2_AS / 2 + base + 8 * (ASTR / 2) + 4];
            }
#pragma unroll
            for (int j = 0; j < 4; j++) {
                int col = wn * 32 + j * 8 + (lane >> 2);
                int base = col * (ASTR / 2) + (lane & 3) + kof;
                uint32_t bb0 = su[G2_BB / 2 + base], bb1 = su[G2_BB / 2 + base + 4];
                uint32_t bs0 = su[G2_BS / 2 + base], bs1 = su[G2_BS / 2 + base + 4];
#pragma unroll
                for (int m = 0; m < 2; m++) {
                    mma16816(acc[m][j], Ab[m], bb0, bb1);
                    mma16816(acc[m][j], Ab[m], bs0, bs1);
                    mma16816(acc[m][j], As[m], bb0, bb1);
                }
            }
        }
        if (c + 1 < NC) stash((c + 1) & 1);
        __syncthreads();
    }

    // epilogue: weighted atomicAdd into out
#pragma unroll
    for (int m = 0; m < 2; m++) {
        int rA = row0 + wm * 32 + m * 16 + (lane >> 2);
        int rB = rA + 8;
        int tA = g_row_token[rA], tB = g_row_token[rB];
        float wA = g_row_weight[rA], wB = g_row_weight[rB];
#pragma unroll
        for (int j = 0; j < 4; j++) {
            int col = n0 + wn * 32 + j * 8 + (lane & 3) * 2;
            if (tA >= 0) {
                float* p = out + (size_t)tA * HDIM + col;
                atomicAdd(p + 0, acc[m][j][0] * wA);
                atomicAdd(p + 1, acc[m][j][1] * wA);
            }
            if (tB >= 0) {
                float* p = out + (size_t)tB * HDIM + col;
                atomicAdd(p + 0, acc[m][j][2] * wB);
                atomicAdd(p + 1, acc[m][j][3] * wB);
            }
        }
    }
}

// ---------------- launcher ----------------
extern "C" void kernel_launch(void* const* d_in, const int* in_sizes, int n_in,
                              void* d_out, int out_size) {
    const float* x      = (const float*)d_in[0];
    const float* gate_w = (const float*)d_in[1];
    const float* w1     = (const float*)d_in[2];
    const float* w2     = (const float*)d_in[3];
    const float* w3     = (const float*)d_in[4];
    float* out          = (float*)d_out;
    float* logits_out   = out + (size_t)OUT_ELEMS;
    (void)in_sizes; (void)n_in; (void)out_size;

    const int smem1 = 2 * G1_STAGE * 2;   // bytes: 81920
    const int smem2 = 2 * G2_STAGE * 2;   // bytes: 61440
    cudaFuncSetAttribute(gemm1_mma, cudaFuncAttributeMaxDynamicSharedMemorySize, smem1);
    cudaFuncSetAttribute(gemm2_mma, cudaFuncAttributeMaxDynamicSharedMemorySize, smem2);

    init_kernel<<<(OUT_ELEMS + 255) / 256, 256>>>(out);
    router_kernel<<<T_TOK / 8, 256>>>(x, gate_w, logits_out);
    scan_kernel<<<1, 1>>>();
    scatter_kernel<<<(T_TOK + 255) / 256, 256>>>();

    dim3 g1(ROWS_MAX / BM, FDIM / 64);
    gemm1_mma<<<g1, 256, smem1>>>(x, w1, w3);
    dim3 g2(ROWS_MAX / BM, HDIM / 64);
    gemm2_mma<<<g2, 256, smem2>>>(w2, out);
}